// round 10
// baseline (speedup 1.0000x reference)
#include <cuda_runtime.h>
#include <cstdint>

#define Bz 8
#define Sq 1024
#define Ed 768
#define Hh 12
#define Dd 64
#define N3 2304
#define TOPK 409
#define QT 32      // q rows per CTA
#define KTT 128
#define KVP 72     // K/V smem row stride: 8*tig+gid -> conflict-free PV loads
#define QSP 68     // q smem row stride: 4*gid+tig conflict-free
#define SCP 1028   // scores row stride

#define ASTR 20
#define BSTR 136

// ---- scratch (allocation-free rule: __device__ globals) ----
__device__ float g_Q[Bz*Hh*Sq*Dd];
__device__ float g_K[Bz*Hh*Sq*Dd];
__device__ float g_V[Bz*Hh*Sq*Dd];
__device__ float g_AO[Bz*Sq*Ed];     // [b,s,h,d] = [8192, 768]

// ---- cp.async helpers ----
__device__ __forceinline__ void cp16(void* smem_dst, const void* gmem_src) {
    unsigned s = (unsigned)__cvta_generic_to_shared(smem_dst);
    asm volatile("cp.async.cg.shared.global [%0], [%1], 16;" :: "r"(s), "l"(gmem_src));
}
__device__ __forceinline__ void cp_commit() { asm volatile("cp.async.commit_group;"); }
template<int N>
__device__ __forceinline__ void cp_wait() { asm volatile("cp.async.wait_group %0;" :: "n"(N)); }

// ---- tf32 helpers ----
__device__ __forceinline__ uint32_t f2tf(float x) {
    uint32_t r; asm("cvt.rna.tf32.f32 %0, %1;" : "=r"(r) : "f"(x)); return r;
}
__device__ __forceinline__ void split_tf32(float x, uint32_t& hi, uint32_t& lo) {
    uint32_t h;
    asm("cvt.rna.tf32.f32 %0, %1;" : "=r"(h) : "f"(x));
    float l = x - __uint_as_float(h);
    uint32_t lw;
    asm("cvt.rna.tf32.f32 %0, %1;" : "=r"(lw) : "f"(l));
    hi = h; lo = lw;
}
__device__ __forceinline__ void mma_tf32(float4& d, const uint32_t a[4], const uint32_t b[2]) {
    asm volatile("mma.sync.aligned.m16n8k8.row.col.f32.tf32.tf32.f32 "
                 "{%0,%1,%2,%3}, {%4,%5,%6,%7}, {%8,%9}, {%0,%1,%2,%3};"
                 : "+f"(d.x), "+f"(d.y), "+f"(d.z), "+f"(d.w)
                 : "r"(a[0]), "r"(a[1]), "r"(a[2]), "r"(a[3]), "r"(b[0]), "r"(b[1]));
}

// ============================================================
// 3xTF32 GEMM (unchanged from R7/R9, passing at 475us)
// ============================================================
template<int NDIM, bool SCATTER>
__global__ __launch_bounds__(256, 2) void gemm_tf32(const float* __restrict__ A_in,
                                                    const float* __restrict__ W,
                                                    const float* __restrict__ bias,
                                                    float* __restrict__ out) {
    const float* A = SCATTER ? A_in : (const float*)g_AO;   // device-side symbol!

    __shared__ float As[2][128*ASTR];
    __shared__ float Bs[2][16*BSTR];

    const int t    = threadIdx.x;
    const int warp = t >> 5, lane = t & 31;
    const int gid  = lane >> 2, tig = lane & 3;
    const int m0   = blockIdx.y * 128, n0 = blockIdx.x * 128;
    const int wm   = (warp >> 2) * 64;
    const int wn   = (warp & 3) * 32;

    auto issue = [&](int buf, int kt) {
        #pragma unroll
        for (int i = 0; i < 2; i++) {
            int f = t + 256*i;
            int m = f >> 2, kc = (f & 3) << 2;
            cp16(&As[buf][m*ASTR + kc], &A[(size_t)(m0 + m)*Ed + kt*16 + kc]);
        }
        #pragma unroll
        for (int i = 0; i < 2; i++) {
            int f = t + 256*i;
            int kr = f >> 5, nc = (f & 31) << 2;
            cp16(&Bs[buf][kr*BSTR + nc], &W[(size_t)(kt*16 + kr)*NDIM + n0 + nc]);
        }
        cp_commit();
    };

    float4 acc[4][4];
    #pragma unroll
    for (int i = 0; i < 4; i++)
        #pragma unroll
        for (int j = 0; j < 4; j++) acc[i][j] = make_float4(0.f, 0.f, 0.f, 0.f);

    issue(0, 0);
    const int NT = Ed / 16;
    for (int kt = 0; kt < NT; kt++) {
        if (kt + 1 < NT) { issue((kt + 1) & 1, kt + 1); cp_wait<1>(); }
        else             { cp_wait<0>(); }
        __syncthreads();
        const float* as = As[kt & 1];
        const float* bs = Bs[kt & 1];
        #pragma unroll
        for (int ko = 0; ko < 16; ko += 8) {
            uint32_t Bhi[4][2], Blo[4][2];
            #pragma unroll
            for (int j = 0; j < 4; j++) {
                const int nc = wn + 8*j + gid;
                split_tf32(bs[(ko + tig    )*BSTR + nc], Bhi[j][0], Blo[j][0]);
                split_tf32(bs[(ko + tig + 4)*BSTR + nc], Bhi[j][1], Blo[j][1]);
            }
            #pragma unroll
            for (int i = 0; i < 4; i++) {
                const int r0 = wm + 16*i + gid;
                uint32_t Ahi[4], Alo[4];
                split_tf32(as[ r0     *ASTR + ko + tig    ], Ahi[0], Alo[0]);
                split_tf32(as[(r0 + 8)*ASTR + ko + tig    ], Ahi[1], Alo[1]);
                split_tf32(as[ r0     *ASTR + ko + tig + 4], Ahi[2], Alo[2]);
                split_tf32(as[(r0 + 8)*ASTR + ko + tig + 4], Ahi[3], Alo[3]);
                #pragma unroll
                for (int j = 0; j < 4; j++) {
                    mma_tf32(acc[i][j], Alo, Bhi[j]);
                    mma_tf32(acc[i][j], Ahi, Blo[j]);
                    mma_tf32(acc[i][j], Ahi, Bhi[j]);
                }
            }
        }
        __syncthreads();
    }

    #pragma unroll
    for (int i = 0; i < 4; i++) {
        const int ma = m0 + wm + 16*i + gid;
        const int mb = ma + 8;
        #pragma unroll
        for (int j = 0; j < 4; j++) {
            const int nb = n0 + wn + 8*j + 2*tig;
            const float2 bv = *(const float2*)&bias[nb];
            float2 va = make_float2(acc[i][j].x + bv.x, acc[i][j].y + bv.y);
            float2 vb = make_float2(acc[i][j].z + bv.x, acc[i][j].w + bv.y);
            if (SCATTER) {
                const int which = nb / Ed;
                const int hh    = (nb % Ed) >> 6;
                const int d0    = nb & 63;
                float* dst = (which == 0) ? g_Q : (which == 1) ? g_K : g_V;
                {
                    int bb = ma >> 10, ss = ma & 1023;
                    *(float2*)&dst[(size_t)((bb*Hh + hh)*Sq + ss)*Dd + d0] = va;
                }
                {
                    int bb = mb >> 10, ss = mb & 1023;
                    *(float2*)&dst[(size_t)((bb*Hh + hh)*Sq + ss)*Dd + d0] = vb;
                }
            } else {
                *(float2*)&out[(size_t)ma * NDIM + nb] = va;
                *(float2*)&out[(size_t)mb * NDIM + nb] = vb;
            }
        }
    }
}

// ============================================================
// Fused attention v3: 32 q-rows/CTA, 512 thr, 1 CTA/SM.
// cp.async double-buffered K/V; q frags resident in registers;
// 3xTF32 scores, exact top-k, 1xTF32 PV with pre-tf32 p.
// ============================================================
__global__ __launch_bounds__(512, 1) void attn_kernel() {
    extern __shared__ float sm[];
    float* q_hi = sm;                   // 32*68  = 2176
    float* q_lo = sm + 2176;            // 2176
    float* sc   = sm + 4352;            // 32*1028 = 32896
    float* kv0  = sm + 37248;           // 128*72 = 9216
    float* kv1  = sm + 46464;           // 9216
    float* invs = sm + 55680;           // 32
    // total 55712 floats = 222848 B

    const int t    = threadIdx.x;
    const int warp = t >> 5, lane = t & 31;   // 16 warps
    const int gid  = lane >> 2, tig = lane & 3;
    const int bh = blockIdx.y;
    const int q0 = blockIdx.x * QT;
    const float* Qg = g_Q + (size_t)bh*Sq*Dd;
    const float* Kg = g_K + (size_t)bh*Sq*Dd;
    const float* Vg = g_V + (size_t)bh*Sq*Dd;

    auto cp_tile = [&](float* buf, const float* src, int kt0) {
        #pragma unroll
        for (int i = 0; i < 4; i++) {
            int f = t + 512*i;
            int row = f >> 4, c4 = (f & 15) << 2;
            cp16(&buf[row*KVP + c4], &src[(size_t)(kt0*KTT + row)*Dd + c4]);
        }
        cp_commit();
    };

    // issue K0; stage q (scaled 0.125, pre-split hi/lo)
    cp_tile(kv0, Kg, 0);
    {
        const int prow = t >> 4, pc4 = (t & 15) << 2;   // 32 rows x 16 f4 = 512
        float4 v = *(const float4*)&Qg[(size_t)(q0 + prow)*Dd + pc4];
        v.x *= 0.125f; v.y *= 0.125f; v.z *= 0.125f; v.w *= 0.125f;
        uint32_t h, l;
        split_tf32(v.x, h, l); q_hi[prow*QSP + pc4+0] = __uint_as_float(h); q_lo[prow*QSP + pc4+0] = __uint_as_float(l);
        split_tf32(v.y, h, l); q_hi[prow*QSP + pc4+1] = __uint_as_float(h); q_lo[prow*QSP + pc4+1] = __uint_as_float(l);
        split_tf32(v.z, h, l); q_hi[prow*QSP + pc4+2] = __uint_as_float(h); q_lo[prow*QSP + pc4+2] = __uint_as_float(l);
        split_tf32(v.w, h, l); q_hi[prow*QSP + pc4+3] = __uint_as_float(h); q_lo[prow*QSP + pc4+3] = __uint_as_float(l);
    }
    __syncthreads();

    // preload q fragments for this warp's q-half (loop-invariant!)
    const int qh_  = warp >> 3;          // 0 or 1 (q rows qh_*16 .. +16)
    const int key0 = (warp & 7) * 16;    // 16 keys per warp
    const int r0 = qh_*16 + gid, r1 = r0 + 8;
    uint32_t qfh[8][4], qfl[8][4];
    #pragma unroll
    for (int ks = 0; ks < 8; ks++) {
        qfh[ks][0] = __float_as_uint(q_hi[r0*QSP + ks*8 + tig    ]);
        qfh[ks][1] = __float_as_uint(q_hi[r1*QSP + ks*8 + tig    ]);
        qfh[ks][2] = __float_as_uint(q_hi[r0*QSP + ks*8 + tig + 4]);
        qfh[ks][3] = __float_as_uint(q_hi[r1*QSP + ks*8 + tig + 4]);
        qfl[ks][0] = __float_as_uint(q_lo[r0*QSP + ks*8 + tig    ]);
        qfl[ks][1] = __float_as_uint(q_lo[r1*QSP + ks*8 + tig    ]);
        qfl[ks][2] = __float_as_uint(q_lo[r0*QSP + ks*8 + tig + 4]);
        qfl[ks][3] = __float_as_uint(q_lo[r1*QSP + ks*8 + tig + 4]);
    }

    // ================= scores (3xTF32) =================
    for (int it = 0; it < 8; it++) {
        if (it + 1 < 8) { cp_tile((it & 1) ? kv0 : kv1, Kg, it + 1); cp_wait<1>(); }
        else            { cp_wait<0>(); }
        __syncthreads();
        const float* kb_ = (it & 1) ? kv1 : kv0;

        float4 c0a = make_float4(0.f,0.f,0.f,0.f), c0b = c0a, c1a = c0a, c1b = c0a;
        #pragma unroll
        for (int ks = 0; ks < 8; ks++) {
            uint32_t Bh[2], Bl[2];
            split_tf32(kb_[(key0     + gid)*KVP + ks*8 + tig    ], Bh[0], Bl[0]);
            split_tf32(kb_[(key0     + gid)*KVP + ks*8 + tig + 4], Bh[1], Bl[1]);
            float4& c0 = (ks & 1) ? c0b : c0a;
            mma_tf32(c0, qfl[ks], Bh); mma_tf32(c0, qfh[ks], Bl); mma_tf32(c0, qfh[ks], Bh);
            split_tf32(kb_[(key0 + 8 + gid)*KVP + ks*8 + tig    ], Bh[0], Bl[0]);
            split_tf32(kb_[(key0 + 8 + gid)*KVP + ks*8 + tig + 4], Bh[1], Bl[1]);
            float4& c1 = (ks & 1) ? c1b : c1a;
            mma_tf32(c1, qfl[ks], Bh); mma_tf32(c1, qfh[ks], Bl); mma_tf32(c1, qfh[ks], Bh);
        }
        float4 c0 = make_float4(c0a.x+c0b.x, c0a.y+c0b.y, c0a.z+c0b.z, c0a.w+c0b.w);
        float4 c1 = make_float4(c1a.x+c1b.x, c1a.y+c1b.y, c1a.z+c1b.z, c1a.w+c1b.w);
        const int cb = it*KTT + key0 + 2*tig;
        *(float2*)&sc[r0*SCP + cb    ] = make_float2(c0.x, c0.y);
        *(float2*)&sc[r1*SCP + cb    ] = make_float2(c0.z, c0.w);
        *(float2*)&sc[r0*SCP + cb + 8] = make_float2(c1.x, c1.y);
        *(float2*)&sc[r1*SCP + cb + 8] = make_float2(c1.z, c1.w);
        __syncthreads();
    }

    cp_tile(kv0, Vg, 0);   // V0 flies during top-k

    // ====== exact top-k + softmax; p stored pre-rounded to tf32 ======
    {
        const int lane5 = t & 31;
        #pragma unroll 1
        for (int r = warp*2; r < warp*2 + 2; r++) {
            float* row = sc + r*SCP;
            unsigned u[32];
            float mx = -3.4e38f;
            #pragma unroll
            for (int i = 0; i < 32; i++) {
                float f = row[i*32 + lane5];
                mx = fmaxf(mx, f);
                unsigned b = __float_as_uint(f);
                u[i] = b ^ (unsigned)(((int)b >> 31) | (int)0x80000000);
            }
            #pragma unroll
            for (int o = 16; o; o >>= 1) mx = fmaxf(mx, __shfl_xor_sync(0xffffffffu, mx, o));

            unsigned pref = 0;
            #pragma unroll 1
            for (int bb = 31; bb >= 0; bb--) {
                unsigned trial = pref | (1u << bb);
                int c = 0;
                #pragma unroll
                for (int i = 0; i < 32; i++) c += (u[i] >= trial) ? 1 : 0;
                c = (int)__reduce_add_sync(0xffffffffu, (unsigned)c);
                if (c >= TOPK) pref = trial;
            }

            float ssum = 0.f;
            #pragma unroll
            for (int i = 0; i < 32; i++) {
                float p = 0.f;
                if (u[i] >= pref) {
                    unsigned b = (u[i] & 0x80000000u) ? (u[i] ^ 0x80000000u) : ~u[i];
                    p = __expf(__uint_as_float(b) - mx);
                }
                ssum += p;
                row[i*32 + lane5] = __uint_as_float(f2tf(p));   // pre-tf32 for PV
            }
            #pragma unroll
            for (int o = 16; o; o >>= 1) ssum += __shfl_xor_sync(0xffffffffu, ssum, o);
            if (lane5 == 0) invs[r] = 1.f / ssum;
        }
    }
    cp_wait<0>(); __syncthreads();   // V0 in smem; p + invs visible

    // ================= PV (1xTF32, p already tf32) =================
    const int dc = (warp & 7) * 8;   // warp's 8 d-columns; q-half = qh_
    float4 oc[4];
    #pragma unroll
    for (int j = 0; j < 4; j++) oc[j] = make_float4(0.f,0.f,0.f,0.f);

    for (int it = 0; it < 8; it++) {
        if (it + 1 < 8) { cp_tile((it & 1) ? kv0 : kv1, Vg, it + 1); cp_wait<1>(); }
        else            { cp_wait<0>(); }
        __syncthreads();
        const float* kb_ = (it & 1) ? kv1 : kv0;
        const int kb = it*KTT;
        #pragma unroll
        for (int ks = 0; ks < 16; ks++) {
            uint32_t Ap[4], Bv[2];
            Ap[0] = __float_as_uint(sc[r0*SCP + kb + ks*8 + tig    ]);
            Ap[1] = __float_as_uint(sc[r1*SCP + kb + ks*8 + tig    ]);
            Ap[2] = __float_as_uint(sc[r0*SCP + kb + ks*8 + tig + 4]);
            Ap[3] = __float_as_uint(sc[r1*SCP + kb + ks*8 + tig + 4]);
            Bv[0] = f2tf(kb_[(ks*8 + tig    )*KVP + dc + gid]);
            Bv[1] = f2tf(kb_[(ks*8 + tig + 4)*KVP + dc + gid]);
            mma_tf32(oc[ks >> 2], Ap, Bv);
        }
        __syncthreads();
    }

    // epilogue
    {
        float4 o;
        o.x = (oc[0].x + oc[1].x) + (oc[2].x + oc[3].x);
        o.y = (oc[0].y + oc[1].y) + (oc[2].y + oc[3].y);
        o.z = (oc[0].z + oc[1].z) + (oc[2].z + oc[3].z);
        o.w = (oc[0].w + oc[1].w) + (oc[2].w + oc[3].w);
        const int bb = bh / Hh, hh = bh % Hh;
        const float iv0 = invs[r0], iv1 = invs[r1];
        const int d0 = dc + 2*tig;
        *(float2*)&g_AO[(size_t)((bb*Sq + q0 + r0)*Hh + hh)*Dd + d0] = make_float2(o.x*iv0, o.y*iv0);
        *(float2*)&g_AO[(size_t)((bb*Sq + q0 + r1)*Hh + hh)*Dd + d0] = make_float2(o.z*iv1, o.w*iv1);
    }
}

// ============================================================
// launch
// ============================================================
extern "C" void kernel_launch(void* const* d_in, const int* in_sizes, int n_in,
                              void* d_out, int out_size) {
    const float* hidden = (const float*)d_in[0];
    const float* Wqkv   = (const float*)d_in[1];
    const float* bqkv   = (const float*)d_in[2];
    const float* Wproj  = (const float*)d_in[3];
    const float* bproj  = (const float*)d_in[4];
    float* out = (float*)d_out;

    const int attn_smem = 55712 * (int)sizeof(float);  // 222848 B
    cudaFuncSetAttribute(attn_kernel, cudaFuncAttributeMaxDynamicSharedMemorySize, attn_smem);

    gemm_tf32<N3, true ><<<dim3(N3/128, (Bz*Sq)/128), 256>>>(hidden, Wqkv, bqkv, nullptr);
    attn_kernel<<<dim3(Sq/QT, Bz*Hh), 512, attn_smem>>>();
    gemm_tf32<Ed, false><<<dim3(Ed/128, (Bz*Sq)/128), 256>>>(nullptr, Wproj, bproj, out);
}

// round 11
// speedup vs baseline: 1.1736x; 1.1736x over previous
#include <cuda_runtime.h>
#include <cstdint>

#define Bz 8
#define Sq 1024
#define Ed 768
#define Hh 12
#define Dd 64
#define N3 2304
#define TOPK 409
#define QT 32      // q rows per CTA
#define KTT 128
#define KVP 72     // K/V smem row stride
#define QSP 68     // q smem row stride
#define SCP 1028   // scores row stride

#define ASTR 20
#define BSTR 136

// ---- scratch (allocation-free rule: __device__ globals) ----
__device__ float g_Q[Bz*Hh*Sq*Dd];
__device__ float g_K[Bz*Hh*Sq*Dd];
__device__ float g_V[Bz*Hh*Sq*Dd];
__device__ float g_AO[Bz*Sq*Ed];     // [b,s,h,d] = [8192, 768]

// ---- cp.async helpers ----
__device__ __forceinline__ void cp16(void* smem_dst, const void* gmem_src) {
    unsigned s = (unsigned)__cvta_generic_to_shared(smem_dst);
    asm volatile("cp.async.cg.shared.global [%0], [%1], 16;" :: "r"(s), "l"(gmem_src));
}
__device__ __forceinline__ void cp_commit() { asm volatile("cp.async.commit_group;"); }
template<int N>
__device__ __forceinline__ void cp_wait() { asm volatile("cp.async.wait_group %0;" :: "n"(N)); }

// ---- tf32 helpers ----
__device__ __forceinline__ uint32_t f2tf(float x) {
    uint32_t r; asm("cvt.rna.tf32.f32 %0, %1;" : "=r"(r) : "f"(x)); return r;
}
__device__ __forceinline__ void split_tf32(float x, uint32_t& hi, uint32_t& lo) {
    uint32_t h;
    asm("cvt.rna.tf32.f32 %0, %1;" : "=r"(h) : "f"(x));
    float l = x - __uint_as_float(h);
    uint32_t lw;
    asm("cvt.rna.tf32.f32 %0, %1;" : "=r"(lw) : "f"(l));
    hi = h; lo = lw;
}
__device__ __forceinline__ void mma_tf32(float4& d, const uint32_t a[4], const uint32_t b[2]) {
    asm volatile("mma.sync.aligned.m16n8k8.row.col.f32.tf32.tf32.f32 "
                 "{%0,%1,%2,%3}, {%4,%5,%6,%7}, {%8,%9}, {%0,%1,%2,%3};"
                 : "+f"(d.x), "+f"(d.y), "+f"(d.z), "+f"(d.w)
                 : "r"(a[0]), "r"(a[1]), "r"(a[2]), "r"(a[3]), "r"(b[0]), "r"(b[1]));
}

// ---- 32x32 bit-matrix transpose (Hacker's Delight 7-7) ----
// Property (element-traced): input word i bit b  ->  output word (31-b) bit (31-i).
template<int J>
__device__ __forceinline__ void tstage(unsigned a[32], unsigned m) {
    #pragma unroll
    for (int g = 0; g < 16; g++) {
        const int k = ((g & ~(J - 1)) << 1) | (g & (J - 1));
        unsigned t = (a[k] ^ (a[k + J] >> J)) & m;
        a[k]     ^= t;
        a[k + J] ^= (t << J);
    }
}
__device__ __forceinline__ void bit_transpose32(unsigned a[32]) {
    tstage<16>(a, 0x0000FFFFu);
    tstage<8> (a, 0x00FF00FFu);
    tstage<4> (a, 0x0F0F0F0Fu);
    tstage<2> (a, 0x33333333u);
    tstage<1> (a, 0x55555555u);
}

// ============================================================
// 3xTF32 GEMM (unchanged from R7/R9, passing at 475us)
// ============================================================
template<int NDIM, bool SCATTER>
__global__ __launch_bounds__(256, 2) void gemm_tf32(const float* __restrict__ A_in,
                                                    const float* __restrict__ W,
                                                    const float* __restrict__ bias,
                                                    float* __restrict__ out) {
    const float* A = SCATTER ? A_in : (const float*)g_AO;   // device-side symbol!

    __shared__ float As[2][128*ASTR];
    __shared__ float Bs[2][16*BSTR];

    const int t    = threadIdx.x;
    const int warp = t >> 5, lane = t & 31;
    const int gid  = lane >> 2, tig = lane & 3;
    const int m0   = blockIdx.y * 128, n0 = blockIdx.x * 128;
    const int wm   = (warp >> 2) * 64;
    const int wn   = (warp & 3) * 32;

    auto issue = [&](int buf, int kt) {
        #pragma unroll
        for (int i = 0; i < 2; i++) {
            int f = t + 256*i;
            int m = f >> 2, kc = (f & 3) << 2;
            cp16(&As[buf][m*ASTR + kc], &A[(size_t)(m0 + m)*Ed + kt*16 + kc]);
        }
        #pragma unroll
        for (int i = 0; i < 2; i++) {
            int f = t + 256*i;
            int kr = f >> 5, nc = (f & 31) << 2;
            cp16(&Bs[buf][kr*BSTR + nc], &W[(size_t)(kt*16 + kr)*NDIM + n0 + nc]);
        }
        cp_commit();
    };

    float4 acc[4][4];
    #pragma unroll
    for (int i = 0; i < 4; i++)
        #pragma unroll
        for (int j = 0; j < 4; j++) acc[i][j] = make_float4(0.f, 0.f, 0.f, 0.f);

    issue(0, 0);
    const int NT = Ed / 16;
    for (int kt = 0; kt < NT; kt++) {
        if (kt + 1 < NT) { issue((kt + 1) & 1, kt + 1); cp_wait<1>(); }
        else             { cp_wait<0>(); }
        __syncthreads();
        const float* as = As[kt & 1];
        const float* bs = Bs[kt & 1];
        #pragma unroll
        for (int ko = 0; ko < 16; ko += 8) {
            uint32_t Bhi[4][2], Blo[4][2];
            #pragma unroll
            for (int j = 0; j < 4; j++) {
                const int nc = wn + 8*j + gid;
                split_tf32(bs[(ko + tig    )*BSTR + nc], Bhi[j][0], Blo[j][0]);
                split_tf32(bs[(ko + tig + 4)*BSTR + nc], Bhi[j][1], Blo[j][1]);
            }
            #pragma unroll
            for (int i = 0; i < 4; i++) {
                const int r0 = wm + 16*i + gid;
                uint32_t Ahi[4], Alo[4];
                split_tf32(as[ r0     *ASTR + ko + tig    ], Ahi[0], Alo[0]);
                split_tf32(as[(r0 + 8)*ASTR + ko + tig    ], Ahi[1], Alo[1]);
                split_tf32(as[ r0     *ASTR + ko + tig + 4], Ahi[2], Alo[2]);
                split_tf32(as[(r0 + 8)*ASTR + ko + tig + 4], Ahi[3], Alo[3]);
                #pragma unroll
                for (int j = 0; j < 4; j++) {
                    mma_tf32(acc[i][j], Alo, Bhi[j]);
                    mma_tf32(acc[i][j], Ahi, Blo[j]);
                    mma_tf32(acc[i][j], Ahi, Bhi[j]);
                }
            }
        }
        __syncthreads();
    }

    #pragma unroll
    for (int i = 0; i < 4; i++) {
        const int ma = m0 + wm + 16*i + gid;
        const int mb = ma + 8;
        #pragma unroll
        for (int j = 0; j < 4; j++) {
            const int nb = n0 + wn + 8*j + 2*tig;
            const float2 bv = *(const float2*)&bias[nb];
            float2 va = make_float2(acc[i][j].x + bv.x, acc[i][j].y + bv.y);
            float2 vb = make_float2(acc[i][j].z + bv.x, acc[i][j].w + bv.y);
            if (SCATTER) {
                const int which = nb / Ed;
                const int hh    = (nb % Ed) >> 6;
                const int d0    = nb & 63;
                float* dst = (which == 0) ? g_Q : (which == 1) ? g_K : g_V;
                {
                    int bb = ma >> 10, ss = ma & 1023;
                    *(float2*)&dst[(size_t)((bb*Hh + hh)*Sq + ss)*Dd + d0] = va;
                }
                {
                    int bb = mb >> 10, ss = mb & 1023;
                    *(float2*)&dst[(size_t)((bb*Hh + hh)*Sq + ss)*Dd + d0] = vb;
                }
            } else {
                *(float2*)&out[(size_t)ma * NDIM + nb] = va;
                *(float2*)&out[(size_t)mb * NDIM + nb] = vb;
            }
        }
    }
}

// ============================================================
// Fused attention v4: as R10, but top-k via bit-plane radix
// select with early exit (exact, bit-identical selection).
// ============================================================
__global__ __launch_bounds__(512, 1) void attn_kernel() {
    extern __shared__ float sm[];
    float* q_hi = sm;                   // 32*68  = 2176
    float* q_lo = sm + 2176;            // 2176
    float* sc   = sm + 4352;            // 32*1028 = 32896
    float* kv0  = sm + 37248;           // 128*72 = 9216
    float* kv1  = sm + 46464;           // 9216
    float* invs = sm + 55680;           // 32

    const int t    = threadIdx.x;
    const int warp = t >> 5, lane = t & 31;   // 16 warps
    const int gid  = lane >> 2, tig = lane & 3;
    const int bh = blockIdx.y;
    const int q0 = blockIdx.x * QT;
    const float* Qg = g_Q + (size_t)bh*Sq*Dd;
    const float* Kg = g_K + (size_t)bh*Sq*Dd;
    const float* Vg = g_V + (size_t)bh*Sq*Dd;

    auto cp_tile = [&](float* buf, const float* src, int kt0) {
        #pragma unroll
        for (int i = 0; i < 4; i++) {
            int f = t + 512*i;
            int row = f >> 4, c4 = (f & 15) << 2;
            cp16(&buf[row*KVP + c4], &src[(size_t)(kt0*KTT + row)*Dd + c4]);
        }
        cp_commit();
    };

    // issue K0; stage q (scaled 0.125, pre-split hi/lo)
    cp_tile(kv0, Kg, 0);
    {
        const int prow = t >> 4, pc4 = (t & 15) << 2;
        float4 v = *(const float4*)&Qg[(size_t)(q0 + prow)*Dd + pc4];
        v.x *= 0.125f; v.y *= 0.125f; v.z *= 0.125f; v.w *= 0.125f;
        uint32_t h, l;
        split_tf32(v.x, h, l); q_hi[prow*QSP + pc4+0] = __uint_as_float(h); q_lo[prow*QSP + pc4+0] = __uint_as_float(l);
        split_tf32(v.y, h, l); q_hi[prow*QSP + pc4+1] = __uint_as_float(h); q_lo[prow*QSP + pc4+1] = __uint_as_float(l);
        split_tf32(v.z, h, l); q_hi[prow*QSP + pc4+2] = __uint_as_float(h); q_lo[prow*QSP + pc4+2] = __uint_as_float(l);
        split_tf32(v.w, h, l); q_hi[prow*QSP + pc4+3] = __uint_as_float(h); q_lo[prow*QSP + pc4+3] = __uint_as_float(l);
    }
    __syncthreads();

    // preload q fragments for this warp's q-half (loop-invariant)
    const int qh_  = warp >> 3;
    const int key0 = (warp & 7) * 16;
    const int r0 = qh_*16 + gid, r1 = r0 + 8;
    uint32_t qfh[8][4], qfl[8][4];
    #pragma unroll
    for (int ks = 0; ks < 8; ks++) {
        qfh[ks][0] = __float_as_uint(q_hi[r0*QSP + ks*8 + tig    ]);
        qfh[ks][1] = __float_as_uint(q_hi[r1*QSP + ks*8 + tig    ]);
        qfh[ks][2] = __float_as_uint(q_hi[r0*QSP + ks*8 + tig + 4]);
        qfh[ks][3] = __float_as_uint(q_hi[r1*QSP + ks*8 + tig + 4]);
        qfl[ks][0] = __float_as_uint(q_lo[r0*QSP + ks*8 + tig    ]);
        qfl[ks][1] = __float_as_uint(q_lo[r1*QSP + ks*8 + tig    ]);
        qfl[ks][2] = __float_as_uint(q_lo[r0*QSP + ks*8 + tig + 4]);
        qfl[ks][3] = __float_as_uint(q_lo[r1*QSP + ks*8 + tig + 4]);
    }

    // ================= scores (3xTF32) =================
    for (int it = 0; it < 8; it++) {
        if (it + 1 < 8) { cp_tile((it & 1) ? kv0 : kv1, Kg, it + 1); cp_wait<1>(); }
        else            { cp_wait<0>(); }
        __syncthreads();
        const float* kb_ = (it & 1) ? kv1 : kv0;

        float4 c0a = make_float4(0.f,0.f,0.f,0.f), c0b = c0a, c1a = c0a, c1b = c0a;
        #pragma unroll
        for (int ks = 0; ks < 8; ks++) {
            uint32_t Bh[2], Bl[2];
            split_tf32(kb_[(key0     + gid)*KVP + ks*8 + tig    ], Bh[0], Bl[0]);
            split_tf32(kb_[(key0     + gid)*KVP + ks*8 + tig + 4], Bh[1], Bl[1]);
            float4& c0 = (ks & 1) ? c0b : c0a;
            mma_tf32(c0, qfl[ks], Bh); mma_tf32(c0, qfh[ks], Bl); mma_tf32(c0, qfh[ks], Bh);
            split_tf32(kb_[(key0 + 8 + gid)*KVP + ks*8 + tig    ], Bh[0], Bl[0]);
            split_tf32(kb_[(key0 + 8 + gid)*KVP + ks*8 + tig + 4], Bh[1], Bl[1]);
            float4& c1 = (ks & 1) ? c1b : c1a;
            mma_tf32(c1, qfl[ks], Bh); mma_tf32(c1, qfh[ks], Bl); mma_tf32(c1, qfh[ks], Bh);
        }
        float4 c0 = make_float4(c0a.x+c0b.x, c0a.y+c0b.y, c0a.z+c0b.z, c0a.w+c0b.w);
        float4 c1 = make_float4(c1a.x+c1b.x, c1a.y+c1b.y, c1a.z+c1b.z, c1a.w+c1b.w);
        const int cb = it*KTT + key0 + 2*tig;
        *(float2*)&sc[r0*SCP + cb    ] = make_float2(c0.x, c0.y);
        *(float2*)&sc[r1*SCP + cb    ] = make_float2(c0.z, c0.w);
        *(float2*)&sc[r0*SCP + cb + 8] = make_float2(c1.x, c1.y);
        *(float2*)&sc[r1*SCP + cb + 8] = make_float2(c1.z, c1.w);
        __syncthreads();
    }

    cp_tile(kv0, Vg, 0);   // V0 flies during top-k

    // ====== exact top-k via bit-plane radix select + softmax ======
    {
        const int lane5 = t & 31;
        #pragma unroll 1
        for (int r = warp*2; r < warp*2 + 2; r++) {
            float* row = sc + r*SCP;
            unsigned u[32], tp[32];
            float mx = -3.4e38f;
            #pragma unroll
            for (int i = 0; i < 32; i++) {
                float f = row[i*32 + lane5];
                mx = fmaxf(mx, f);
                unsigned b = __float_as_uint(f);
                u[i] = b ^ (unsigned)(((int)b >> 31) | (int)0x80000000);
                tp[i] = u[i];
            }
            #pragma unroll
            for (int o = 16; o; o >>= 1) mx = fmaxf(mx, __shfl_xor_sync(0xffffffffu, mx, o));

            // planes: tp[31-b] holds bit b of all 32 values (bit 31-i <-> value i)
            bit_transpose32(tp);

            unsigned active = 0xffffffffu, pref = 0;
            int kr = TOPK, asz = 1024;
            #pragma unroll
            for (int idx = 0; idx < 32; idx++) {          // bit b = 31-idx
                unsigned s = active & tp[idx];
                int ctot = (int)__reduce_add_sync(0xffffffffu, (unsigned)__popc(s));
                if (ctot >= kr) { active = s; asz = ctot; pref |= (1u << (31 - idx)); }
                else            { kr -= ctot; active &= ~s; asz -= ctot; }
                if (asz == kr) break;                      // all actives are in top-k
            }
            // exact kth key = min{u >= pref} (actives + strictly-greater set)
            unsigned mn = 0xffffffffu;
            #pragma unroll
            for (int i = 0; i < 32; i++)
                if (u[i] >= pref) mn = min(mn, u[i]);
            mn = __reduce_min_sync(0xffffffffu, mn);

            float ssum = 0.f;
            #pragma unroll
            for (int i = 0; i < 32; i++) {
                float p = 0.f;
                if (u[i] >= mn) {
                    unsigned b = (u[i] & 0x80000000u) ? (u[i] ^ 0x80000000u) : ~u[i];
                    p = __expf(__uint_as_float(b) - mx);
                }
                ssum += p;
                row[i*32 + lane5] = __uint_as_float(f2tf(p));   // pre-tf32 for PV
            }
            #pragma unroll
            for (int o = 16; o; o >>= 1) ssum += __shfl_xor_sync(0xffffffffu, ssum, o);
            if (lane5 == 0) invs[r] = 1.f / ssum;
        }
    }
    cp_wait<0>(); __syncthreads();   // V0 in smem; p + invs visible

    // ================= PV (1xTF32, p already tf32) =================
    const int dc = (warp & 7) * 8;
    float4 oc[4];
    #pragma unroll
    for (int j = 0; j < 4; j++) oc[j] = make_float4(0.f,0.f,0.f,0.f);

    for (int it = 0; it < 8; it++) {
        if (it + 1 < 8) { cp_tile((it & 1) ? kv0 : kv1, Vg, it + 1); cp_wait<1>(); }
        else            { cp_wait<0>(); }
        __syncthreads();
        const float* kb_ = (it & 1) ? kv1 : kv0;
        const int kb = it*KTT;
        #pragma unroll
        for (int ks = 0; ks < 16; ks++) {
            uint32_t Ap[4], Bv[2];
            Ap[0] = __float_as_uint(sc[r0*SCP + kb + ks*8 + tig    ]);
            Ap[1] = __float_as_uint(sc[r1*SCP + kb + ks*8 + tig    ]);
            Ap[2] = __float_as_uint(sc[r0*SCP + kb + ks*8 + tig + 4]);
            Ap[3] = __float_as_uint(sc[r1*SCP + kb + ks*8 + tig + 4]);
            Bv[0] = f2tf(kb_[(ks*8 + tig    )*KVP + dc + gid]);
            Bv[1] = f2tf(kb_[(ks*8 + tig + 4)*KVP + dc + gid]);
            mma_tf32(oc[ks >> 2], Ap, Bv);
        }
        __syncthreads();
    }

    // epilogue
    {
        float4 o;
        o.x = (oc[0].x + oc[1].x) + (oc[2].x + oc[3].x);
        o.y = (oc[0].y + oc[1].y) + (oc[2].y + oc[3].y);
        o.z = (oc[0].z + oc[1].z) + (oc[2].z + oc[3].z);
        o.w = (oc[0].w + oc[1].w) + (oc[2].w + oc[3].w);
        const int bb = bh / Hh, hh = bh % Hh;
        const float iv0 = invs[r0], iv1 = invs[r1];
        const int d0 = dc + 2*tig;
        *(float2*)&g_AO[(size_t)((bb*Sq + q0 + r0)*Hh + hh)*Dd + d0] = make_float2(o.x*iv0, o.y*iv0);
        *(float2*)&g_AO[(size_t)((bb*Sq + q0 + r1)*Hh + hh)*Dd + d0] = make_float2(o.z*iv1, o.w*iv1);
    }
}

// ============================================================
// launch
// ============================================================
extern "C" void kernel_launch(void* const* d_in, const int* in_sizes, int n_in,
                              void* d_out, int out_size) {
    const float* hidden = (const float*)d_in[0];
    const float* Wqkv   = (const float*)d_in[1];
    const float* bqkv   = (const float*)d_in[2];
    const float* Wproj  = (const float*)d_in[3];
    const float* bproj  = (const float*)d_in[4];
    float* out = (float*)d_out;

    const int attn_smem = 55712 * (int)sizeof(float);  // 222848 B
    cudaFuncSetAttribute(attn_kernel, cudaFuncAttributeMaxDynamicSharedMemorySize, attn_smem);

    gemm_tf32<N3, true ><<<dim3(N3/128, (Bz*Sq)/128), 256>>>(hidden, Wqkv, bqkv, nullptr);
    attn_kernel<<<dim3(Sq/QT, Bz*Hh), 512, attn_smem>>>();
    gemm_tf32<Ed, false><<<dim3(Ed/128, (Bz*Sq)/128), 256>>>(nullptr, Wproj, bproj, out);
}